// round 15
// baseline (speedup 1.0000x reference)
#include <cuda_runtime.h>
#include <cuda_fp16.h>
#include <cstdint>

#define BB 8
#define KK 5
#define TT 40
#define VV 32000
#define EE 256
#define HH 512
#define AA 512
#define GG 40
#define NEGF (-1e9f)
#define NB 125
#define NTH 512
#define NT 5
#define NVT 2000

__device__ __forceinline__ bool better(float av, int ai, float bv, int bi) {
    return (av > bv) || (av == bv && ai < bi);
}
__device__ __forceinline__ void ins5(float* tv, int* ti, float v, int i) {
    if (better(v, i, tv[4], ti[4])) {
        tv[4] = v; ti[4] = i;
        #pragma unroll
        for (int j = 4; j > 0; j--)
            if (better(tv[j], ti[j], tv[j-1], ti[j-1])) {
                float fv = tv[j]; tv[j] = tv[j-1]; tv[j-1] = fv;
                int fi = ti[j]; ti[j] = ti[j-1]; ti[j-1] = fi;
            }
    }
}
__device__ __forceinline__ void warp_top5(float* tv, int* ti, float* rv, int* ri) {
    int hp = 0;
    #pragma unroll
    for (int s5 = 0; s5 < 5; s5++) {
        float bv = (hp < 5) ? tv[hp] : -1e38f;
        int   bi = (hp < 5) ? ti[hp] : 0x7fffffff;
        float wv = bv; int wi = bi;
        for (int o = 16; o; o >>= 1) {
            float ov = __shfl_xor_sync(~0u, wv, o);
            int   oi = __shfl_xor_sync(~0u, wi, o);
            if (better(ov, oi, wv, wi)) { wv = ov; wi = oi; }
        }
        rv[s5] = wv; ri[s5] = wi;
        if (hp < 5 && wi == bi && wv == bv) hp++;
    }
}
#define MMA16(c, A, b0, b1) \
    asm volatile("mma.sync.aligned.m16n8k16.row.col.f32.f16.f16.f32 " \
        "{%0,%1,%2,%3},{%4,%5,%6,%7},{%8,%9},{%0,%1,%2,%3};" \
        : "+f"((c)[0]), "+f"((c)[1]), "+f"((c)[2]), "+f"((c)[3]) \
        : "r"((A).x), "r"((A).y), "r"((A).z), "r"((A).w), "r"(b0), "r"(b1))

// ---------------- device state ----------------
__device__ float g_hn[2][GG*HH];
__device__ float g_gp[12][GG*1536];                 // 0-3: gi (token rows); 4-11: gh (RAW rows)
__device__ __align__(16) uint4 g_pa[(size_t)NVT*2048];  // per vtile: [ks][0..31]=Ah, [ks][32..63]=Al
__device__ __align__(16) __half g_pb[NT*32*32*8];   // [e]{bh0..3, bl0..3}
__device__ __align__(16) float g_out_all[(size_t)TT*GG*VV];
__device__ float g_pm[NB*GG];
__device__ float g_ps[NB*GG];
__device__ float g_pv[NB*GG*5];
__device__ int   g_pi[NB*GG*5];
__device__ float g_tv[GG][5];
__device__ int   g_ti[GG][5];
__device__ float g_mx[GG];
__device__ float g_ls[GG];
__device__ int   g_org_all[TT*BB*KK];
__device__ int   g_tok_all[TT*BB*KK];
__device__ int   g_bt_slot[BB*KK*TT];
__device__ int   g_bt_tok [BB*KK*TT];
__device__ int   g_flags[NB];
__device__ int   g_rel;

// flag-array barrier (execution-proven): parallel arrivals, block 0 aggregates.
__device__ __forceinline__ void gbar(int gen) {
    __syncthreads();
    if (threadIdx.x == 0) {
        __threadfence();
        *(volatile int*)&g_flags[blockIdx.x] = gen;
    }
    if (blockIdx.x == 0) {
        if (threadIdx.x < NB)
            while (*(volatile int*)&g_flags[threadIdx.x] < gen) { }
        __syncthreads();
        if (threadIdx.x == 0) { __threadfence(); *(volatile int*)&g_rel = gen; }
    }
    if (threadIdx.x == 0) {
        while (*(volatile int*)&g_rel < gen) { }
        __threadfence();
    }
    __syncthreads();
}

__global__ void k_reset() {
    if (threadIdx.x < NB) g_flags[threadIdx.x] = 0;
    if (threadIdx.x == 0) g_rel = 0;
}

// ---------------- weight fp16-split fragment prep (once; UNSCALED residual) ----------------
__global__ void k_prep(const float* __restrict__ lw) {
    int idx = blockIdx.x*256 + threadIdx.x;
    if (idx >= NVT*2048) return;
    int lane = idx & 31, half = (idx >> 5) & 1, ks = (idx >> 6) & 31, vt = idx >> 11;
    int m0 = vt*16 + (lane >> 2), m1 = m0 + 8;
    int k0 = ks*16 + (lane & 3)*2;
    const float* r0 = &lw[(size_t)m0*HH];
    const float* r1 = &lw[(size_t)m1*HH];
    float w[8] = { r0[k0], r0[k0+1], r1[k0], r1[k0+1],
                   r0[k0+8], r0[k0+9], r1[k0+8], r1[k0+9] };
    uint32_t pk[4];
    #pragma unroll
    for (int p = 0; p < 4; p++) {
        __half h0 = __float2half_rn(w[p*2]),   h1 = __float2half_rn(w[p*2+1]);
        if (half) {
            __half l0 = __float2half_rn(w[p*2]   - __half2float(h0));
            __half l1 = __float2half_rn(w[p*2+1] - __half2float(h1));
            pk[p] = (uint32_t)__half_as_ushort(l0) | ((uint32_t)__half_as_ushort(l1) << 16);
        } else {
            pk[p] = (uint32_t)__half_as_ushort(h0) | ((uint32_t)__half_as_ushort(h1) << 16);
        }
    }
    g_pa[(size_t)vt*2048 + ks*64 + half*32 + lane] = make_uint4(pk[0], pk[1], pk[2], pk[3]);
}

// ---------------- the persistent kernel ----------------
union USm {
    struct { float wt[64][129]; float it[GG*64]; } p0;
    float smd[GG*268];
    float attrs_s[AA];
};

// one GRU-gate GEMM item: 128 gate rows x 64 K
template<int KIN>
__device__ __forceinline__ void gemm_item(
    USm& u, const float* __restrict__ W, int j0, int kk0, int slot,
    const float* __restrict__ hraw, const float* __restrict__ emb, const int* s_tok,
    int tid, int warp, int lane)
{
    for (int idx = tid; idx < 128*16; idx += NTH) {
        int jl = idx >> 4, q = idx & 15;
        float4 w4 = *reinterpret_cast<const float4*>(&W[(size_t)(j0+jl)*KIN + kk0 + q*4]);
        u.p0.wt[q*4+0][jl] = w4.x; u.p0.wt[q*4+1][jl] = w4.y;
        u.p0.wt[q*4+2][jl] = w4.z; u.p0.wt[q*4+3][jl] = w4.w;
    }
    for (int idx = tid; idx < GG*16; idx += NTH) {
        int g = idx >> 4, q = idx & 15;
        const float* src = hraw ? &hraw[(size_t)g*HH] : &emb[(size_t)s_tok[g]*EE];
        *reinterpret_cast<float4*>(&u.p0.it[g*64 + q*4]) =
            *reinterpret_cast<const float4*>(&src[kk0 + q*4]);
    }
    __syncthreads();
    {
        int ty = warp & 7, ci0 = (warp >> 3) * 2;
        float acc[2][5] = {};
        for (int kk = 0; kk < 64; kk++) {
            float wv0 = u.p0.wt[kk][ci0*32 + lane];
            float wv1 = u.p0.wt[kk][(ci0+1)*32 + lane];
            #pragma unroll
            for (int rr = 0; rr < 5; rr++) {
                float xv = u.p0.it[(ty + 8*rr)*64 + kk];
                acc[0][rr] += wv0 * xv;
                acc[1][rr] += wv1 * xv;
            }
        }
        #pragma unroll
        for (int rr = 0; rr < 5; rr++) {
            int g = ty + 8*rr;
            g_gp[slot][g*1536 + j0 + ci0*32 + lane]     = acc[0][rr];
            g_gp[slot][g*1536 + j0 + (ci0+1)*32 + lane] = acc[1][rr];
        }
    }
}

__global__ void __launch_bounds__(NTH)
k_main(const float* __restrict__ attrs, const int* __restrict__ bos,
       const float* __restrict__ emb,
       const float* __restrict__ w_ih, const float* __restrict__ b_ih,
       const float* __restrict__ w_hh, const float* __restrict__ b_hh,
       const float* __restrict__ tw,   const float* __restrict__ tb,
       const float* __restrict__ lb) {
    __shared__ USm u;
    __shared__ float s_bp[GG];
    __shared__ int   s_org[GG], s_tok[GG];

    const int bx = blockIdx.x, tid = threadIdx.x;
    const int warp = tid >> 5, lane = tid & 31;
    int gen = 0;

    if (bx < BB) {
        int b = bx;
        for (int i = tid; i < AA; i += NTH) u.attrs_s[i] = attrs[b*AA + i];
        __syncthreads();
        for (int j = tid; j < HH; j += NTH) {
            const float* wr = &tw[(size_t)j*AA];
            float acc = 0.f;
            for (int a = 0; a < AA; a++) acc += u.attrs_s[a] * wr[a];
            acc += tb[j];
            for (int k = 0; k < KK; k++) g_hn[0][(k*BB + b)*HH + j] = acc;
        }
    }
    if (tid < GG) {
        s_bp[tid]  = (tid < BB) ? 0.f : NEGF;
        s_org[tid] = tid / BB;
        s_tok[tid] = bos[0];
    }
    gbar(++gen);

    // prologue: speculative gh partials for step 0 from raw g_hn[0]
    if (bx >= 5 && bx < 101) {
        int it2 = bx - 5;
        int c = it2 / 12, jt = it2 % 12;
        gemm_item<HH>(u, w_hh, jt*128, c*64, 4 + c, g_hn[0], emb, s_tok, tid, warp, lane);
    }
    gbar(++gen);

    for (int t = 0; t < TT; t++) {
        const int prev = t & 1, cur = prev ^ 1;

        // ===== P0: gi gate GEMM only (48 items, token-dependent) =====
        if (bx < 48) {
            int c = bx / 12, jt = bx % 12;
            gemm_item<EE>(u, w_ih, jt*128, c*64, c, nullptr, emb, s_tok, tid, warp, lane);
        }
        gbar(++gen);

        // ===== P1: gates + hn + B fragment pack (UNSCALED residual) =====
        {
            int gid = bx*164 + tid;
            if (tid < 164 && gid < GG*HH) {
                int g = gid >> 9, j = gid & 511, b = g % BB;
                int graw = s_org[g]*BB + b;
                float gi0 = b_ih[j], gi1 = b_ih[HH+j], gi2 = b_ih[2*HH+j];
                float gh0 = b_hh[j], gh1 = b_hh[HH+j], gh2 = b_hh[2*HH+j];
                #pragma unroll
                for (int c = 0; c < 4; c++) {
                    const float* p = &g_gp[c][g*1536];
                    gi0 += p[j]; gi1 += p[HH+j]; gi2 += p[2*HH+j];
                }
                #pragma unroll
                for (int c = 4; c < 12; c++) {
                    const float* p = &g_gp[c][graw*1536];
                    gh0 += p[j]; gh1 += p[HH+j]; gh2 += p[2*HH+j];
                }
                float hprev = g_hn[prev][graw*HH + j];
                float rg = 1.f / (1.f + expf(-(gi0 + gh0)));
                float zg = 1.f / (1.f + expf(-(gi1 + gh1)));
                float ng = tanhf(gi2 + rg*gh2);
                float hv = (1.f - zg)*ng + zg*hprev;
                g_hn[cur][g*HH + j] = hv;

                int nt = g >> 3, gr = g & 7;
                int ks = j >> 4, rr = j & 15;
                int reg = rr >> 3, i4 = (rr & 7) >> 1, hb = rr & 1;
                int ln = gr*4 + i4;
                int e = (nt*32 + ks)*32 + ln;
                __half bh = __float2half_rn(hv);
                __half bl = __float2half_rn(hv - __half2float(bh));
                g_pb[e*8 + reg*2 + hb]     = bh;
                g_pb[e*8 + 4 + reg*2 + hb] = bl;
            }
        }
        gbar(++gen);

        // ===== P2: vocab MMA (8 warps x 2 mtiles, merged accumulator) + stats =====
        {
            const int item = bx, v0 = item * 256;
            if (warp < 8) {
                const int mt = item*16 + warp*2;
                const uint4* pA = &g_pa[(size_t)mt*2048 + lane];
                const uint4* pB = reinterpret_cast<const uint4*>(g_pb) + lane;
                float acc[2][NT][4] = {};
                #pragma unroll 2
                for (int ks = 0; ks < 32; ks++) {
                    uint4 Ah0 = pA[ks*64],        Al0 = pA[ks*64 + 32];
                    uint4 Ah1 = pA[2048 + ks*64], Al1 = pA[2048 + ks*64 + 32];
                    #pragma unroll
                    for (int nt = 0; nt < NT; nt++) {
                        uint4 B = pB[(nt*32 + ks)*32];
                        MMA16(acc[0][nt], Ah0, B.x, B.y);
                        MMA16(acc[0][nt], Ah0, B.z, B.w);
                        MMA16(acc[0][nt], Al0, B.x, B.y);
                        MMA16(acc[1][nt], Ah1, B.x, B.y);
                        MMA16(acc[1][nt], Ah1, B.z, B.w);
                        MMA16(acc[1][nt], Al1, B.x, B.y);
                    }
                }
                #pragma unroll
                for (int mi = 0; mi < 2; mi++) {
                    #pragma unroll
                    for (int nt = 0; nt < NT; nt++) {
                        #pragma unroll
                        for (int c = 0; c < 4; c++) {
                            int g = nt*8 + (lane & 3)*2 + (c & 1);
                            int vloc = (warp*2 + mi)*16 + (lane >> 2) + 8*(c >> 1);
                            u.smd[g*268 + vloc] = acc[mi][nt][c];
                        }
                    }
                }
            }
            __syncthreads();
            for (int g = warp; g < GG; g += 16) {
                const float4* rp = reinterpret_cast<const float4*>(&u.smd[g*268]);
                float4 x0 = rp[lane], x1 = rp[lane + 32];
                float4 b0 = *reinterpret_cast<const float4*>(&lb[v0 + lane*4]);
                float4 b1 = *reinterpret_cast<const float4*>(&lb[v0 + 128 + lane*4]);
                x0.x += b0.x; x0.y += b0.y; x0.z += b0.z; x0.w += b0.w;
                x1.x += b1.x; x1.y += b1.y; x1.z += b1.z; x1.w += b1.w;
                float* dst = &g_out_all[((size_t)t*GG + g)*VV + v0];
                *reinterpret_cast<float4*>(dst + lane*4)       = x0;
                *reinterpret_cast<float4*>(dst + 128 + lane*4) = x1;

                float vv[8] = {x0.x, x0.y, x0.z, x0.w, x1.x, x1.y, x1.z, x1.w};
                float m = vv[0];
                #pragma unroll
                for (int i = 1; i < 8; i++) m = fmaxf(m, vv[i]);
                for (int o = 16; o; o >>= 1) m = fmaxf(m, __shfl_xor_sync(~0u, m, o));
                float s = 0.f;
                #pragma unroll
                for (int i = 0; i < 8; i++) s += expf(vv[i] - m);
                for (int o = 16; o; o >>= 1) s += __shfl_xor_sync(~0u, s, o);
                float t5[5]; int i5[5];
                #pragma unroll
                for (int i = 0; i < 5; i++) { t5[i] = -1e38f; i5[i] = 0x7fffffff; }
                #pragma unroll
                for (int i = 0; i < 4; i++) ins5(t5, i5, vv[i], v0 + lane*4 + i);
                #pragma unroll
                for (int i = 0; i < 4; i++) ins5(t5, i5, vv[4+i], v0 + 128 + lane*4 + i);
                float rv[5]; int ri[5];
                warp_top5(t5, i5, rv, ri);
                if (lane == 0) {
                    g_pm[item*GG + g] = m;
                    g_ps[item*GG + g] = s;
                    #pragma unroll
                    for (int q = 0; q < 5; q++) {
                        g_pv[(item*GG + g)*5 + q] = rv[q];
                        g_pi[(item*GG + g)*5 + q] = ri[q];
                    }
                }
            }
            __syncthreads();
        }
        gbar(++gen);

        // ===== P3: reduce (blocks 0-4) + speculative gh for t+1 (blocks 5-100) =====
        if (bx < 5) {
            if (warp < 8) {
                int g = bx*8 + warp;
                float m = -1e38f;
                for (int p = lane; p < NB; p += 32) m = fmaxf(m, g_pm[p*GG + g]);
                for (int o = 16; o; o >>= 1) m = fmaxf(m, __shfl_xor_sync(~0u, m, o));
                float s = 0.f;
                float t5[5]; int i5[5];
                #pragma unroll
                for (int i = 0; i < 5; i++) { t5[i] = -1e38f; i5[i] = 0x7fffffff; }
                for (int p = lane; p < NB; p += 32) {
                    s += g_ps[p*GG + g] * expf(g_pm[p*GG + g] - m);
                    #pragma unroll
                    for (int q = 0; q < 5; q++)
                        ins5(t5, i5, g_pv[(p*GG + g)*5 + q], g_pi[(p*GG + g)*5 + q]);
                }
                for (int o = 16; o; o >>= 1) s += __shfl_xor_sync(~0u, s, o);
                float rv[5]; int ri[5];
                warp_top5(t5, i5, rv, ri);
                if (lane == 0) {
                    #pragma unroll
                    for (int q = 0; q < 5; q++) { g_tv[g][q] = rv[q]; g_ti[g][q] = ri[q]; }
                    g_mx[g] = m;
                    g_ls[g] = logf(s);
                }
            }
        } else if (bx < 101 && t < TT-1) {
            int it2 = bx - 5;
            int c = it2 / 12, jt = it2 % 12;
            gemm_item<HH>(u, w_hh, jt*128, c*64, 4 + c, g_hn[cur], emb, s_tok, tid, warp, lane);
        }
        gbar(++gen);

        // ===== combine (redundant per block) =====
        if (tid < BB) {
            int b = tid;
            float cv[KK*KK]; int ct[KK*KK];
            #pragma unroll
            for (int ko = 0; ko < KK; ko++) {
                int gg = ko*BB + b;
                float Mg = g_mx[gg], Lg = g_ls[gg], bpv = s_bp[gg];
                #pragma unroll
                for (int q = 0; q < KK; q++) {
                    cv[ko*KK + q] = bpv + ((g_tv[gg][q] - Mg) - Lg);
                    ct[ko*KK + q] = g_ti[gg][q];
                }
            }
            float nbp[KK]; int norg[KK], ntok[KK];
            bool used[KK*KK] = {};
            #pragma unroll
            for (int kn = 0; kn < KK; kn++) {
                int bf = -1; float bv = 0.f;
                for (int f = 0; f < KK*KK; f++)
                    if (!used[f] && (bf < 0 || cv[f] > bv)) { bv = cv[f]; bf = f; }
                used[bf] = true;
                nbp[kn] = bv; norg[kn] = bf / KK; ntok[kn] = ct[bf];
            }
            #pragma unroll
            for (int kn = 0; kn < KK; kn++) {
                s_bp[kn*BB + b]  = nbp[kn];
                s_org[kn*BB + b] = norg[kn];
                s_tok[kn*BB + b] = ntok[kn];
                if (bx == 0) {
                    g_org_all[t*BB*KK + b*KK + kn] = norg[kn];
                    g_tok_all[t*BB*KK + b*KK + kn] = ntok[kn];
                }
            }
        }
        __syncthreads();
    }

    // ===== backtrack (block 0 only) =====
    if (bx == 0 && tid < BB*KK) {
        int b = tid / KK, k = tid % KK, idx = k;
        for (int t = TT - 1; t >= 0; t--) {
            int o = g_org_all[t*BB*KK + b*KK + idx];
            g_bt_slot[(b*KK + k)*TT + t] = o;
            g_bt_tok [(b*KK + k)*TT + t] = g_tok_all[t*BB*KK + b*KK + idx];
            idx = o;
        }
    }
}

// ---------------- final write ----------------
__global__ void k_write(float* __restrict__ out) {
    int q = blockIdx.x;
    int b = q / (KK*TT), rem = q % (KK*TT);
    int k = rem / TT, t = rem % TT;
    int s = g_bt_slot[(b*KK + k)*TT + t];
    int tok = g_bt_tok[(b*KK + k)*TT + t];
    const float4* src = (const float4*)&g_out_all[((size_t)t*GG + (s*BB + b))*VV];
    size_t N = (size_t)BB*KK*TT*VV;
    size_t off = (((size_t)b*KK + k)*TT + t)*(size_t)VV;
    float4* d0 = (float4*)(out + off);
    float4* d1 = (float4*)(out + N + off);
    float4* d2 = (float4*)(out + 2*N + off);
    for (int i = threadIdx.x; i < VV/4; i += blockDim.x) {
        d0[i] = src[i];
        int vb = i*4;
        float4 h;
        h.x = (vb == tok) ? 1.f : 0.f;  h.y = (vb+1 == tok) ? 1.f : 0.f;
        h.z = (vb+2 == tok) ? 1.f : 0.f; h.w = (vb+3 == tok) ? 1.f : 0.f;
        d1[i] = h; d2[i] = h;
    }
}

// ---------------- launch ----------------
extern "C" void kernel_launch(void* const* d_in, const int* in_sizes, int n_in,
                              void* d_out, int out_size) {
    const float* attrs = (const float*)d_in[0];
    const int*   bos   = (const int*)  d_in[1];
    const float* emb   = (const float*)d_in[4];
    const float* w_ih  = (const float*)d_in[5];
    const float* b_ih  = (const float*)d_in[6];
    const float* w_hh  = (const float*)d_in[7];
    const float* b_hh  = (const float*)d_in[8];
    const float* tw    = (const float*)d_in[9];
    const float* tb    = (const float*)d_in[10];
    const float* lw    = (const float*)d_in[11];
    const float* lb    = (const float*)d_in[12];
    float* out = (float*)d_out;

    k_reset<<<1, 128>>>();
    k_prep<<<(NVT*2048 + 255)/256, 256>>>(lw);
    k_main<<<NB, NTH>>>(attrs, bos, emb, w_ih, b_ih, w_hh, b_hh, tw, tb, lb);
    k_write<<<BB*KK*TT, 256>>>(out);
}

// round 16
// speedup vs baseline: 1.0997x; 1.0997x over previous
#include <cuda_runtime.h>
#include <cuda_fp16.h>
#include <cstdint>

#define BB 8
#define KK 5
#define TT 40
#define VV 32000
#define EE 256
#define HH 512
#define AA 512
#define GG 40
#define NEGF (-1e9f)
#define NB 125
#define NTH 512
#define NT 5
#define NVT 2000

__device__ __forceinline__ bool better(float av, int ai, float bv, int bi) {
    return (av > bv) || (av == bv && ai < bi);
}
__device__ __forceinline__ void ins5(float* tv, int* ti, float v, int i) {
    if (better(v, i, tv[4], ti[4])) {
        tv[4] = v; ti[4] = i;
        #pragma unroll
        for (int j = 4; j > 0; j--)
            if (better(tv[j], ti[j], tv[j-1], ti[j-1])) {
                float fv = tv[j]; tv[j] = tv[j-1]; tv[j-1] = fv;
                int fi = ti[j]; ti[j] = ti[j-1]; ti[j-1] = fi;
            }
    }
}
__device__ __forceinline__ void warp_top5(float* tv, int* ti, float* rv, int* ri) {
    int hp = 0;
    #pragma unroll
    for (int s5 = 0; s5 < 5; s5++) {
        float bv = (hp < 5) ? tv[hp] : -1e38f;
        int   bi = (hp < 5) ? ti[hp] : 0x7fffffff;
        float wv = bv; int wi = bi;
        for (int o = 16; o; o >>= 1) {
            float ov = __shfl_xor_sync(~0u, wv, o);
            int   oi = __shfl_xor_sync(~0u, wi, o);
            if (better(ov, oi, wv, wi)) { wv = ov; wi = oi; }
        }
        rv[s5] = wv; ri[s5] = wi;
        if (hp < 5 && wi == bi && wv == bv) hp++;
    }
}
#define MMA16(c, A, b0, b1) \
    asm volatile("mma.sync.aligned.m16n8k16.row.col.f32.f16.f16.f32 " \
        "{%0,%1,%2,%3},{%4,%5,%6,%7},{%8,%9},{%0,%1,%2,%3};" \
        : "+f"((c)[0]), "+f"((c)[1]), "+f"((c)[2]), "+f"((c)[3]) \
        : "r"((A).x), "r"((A).y), "r"((A).z), "r"((A).w), "r"(b0), "r"(b1))

// ---------------- device state ----------------
__device__ float g_hn[2][GG*HH];
__device__ float g_gp[12][GG*1536];                 // 0-3: gi (token rows); 4-11: gh (RAW rows)
__device__ __align__(16) uint4 g_pa[(size_t)NVT*2048];  // per vtile: [ks][0..31]=Ah, [ks][32..63]=Al
__device__ __align__(16) __half g_pb[NT*32*32*8];   // [e]{bh0..3, bl0..3}
__device__ __align__(16) float g_out_all[(size_t)TT*GG*VV];
__device__ float g_pm[NB*GG];
__device__ float g_ps[NB*GG];
__device__ float g_pv[NB*GG*5];
__device__ int   g_pi[NB*GG*5];
__device__ float g_tv[GG][5];
__device__ int   g_ti[GG][5];
__device__ float g_mx[GG];
__device__ float g_ls[GG];
__device__ int   g_org_all[TT*BB*KK];
__device__ int   g_tok_all[TT*BB*KK];
__device__ int   g_bt_slot[BB*KK*TT];
__device__ int   g_bt_tok [BB*KK*TT];
__device__ int   g_flags[NB];
__device__ int   g_rel;

// flag-array barrier (execution-proven): parallel arrivals, block 0 aggregates.
__device__ __forceinline__ void gbar(int gen) {
    __syncthreads();
    if (threadIdx.x == 0) {
        __threadfence();
        *(volatile int*)&g_flags[blockIdx.x] = gen;
    }
    if (blockIdx.x == 0) {
        if (threadIdx.x < NB)
            while (*(volatile int*)&g_flags[threadIdx.x] < gen) { }
        __syncthreads();
        if (threadIdx.x == 0) { __threadfence(); *(volatile int*)&g_rel = gen; }
    }
    if (threadIdx.x == 0) {
        while (*(volatile int*)&g_rel < gen) { }
        __threadfence();
    }
    __syncthreads();
}

__global__ void k_reset() {
    if (threadIdx.x < NB) g_flags[threadIdx.x] = 0;
    if (threadIdx.x == 0) g_rel = 0;
}

// ---------------- weight fp16-split fragment prep (once; scaled residual) ----------------
__global__ void k_prep(const float* __restrict__ lw) {
    int idx = blockIdx.x*256 + threadIdx.x;
    if (idx >= NVT*2048) return;
    int lane = idx & 31, half = (idx >> 5) & 1, ks = (idx >> 6) & 31, vt = idx >> 11;
    int m0 = vt*16 + (lane >> 2), m1 = m0 + 8;
    int k0 = ks*16 + (lane & 3)*2;
    const float* r0 = &lw[(size_t)m0*HH];
    const float* r1 = &lw[(size_t)m1*HH];
    float w[8] = { r0[k0], r0[k0+1], r1[k0], r1[k0+1],
                   r0[k0+8], r0[k0+9], r1[k0+8], r1[k0+9] };
    uint32_t pk[4];
    #pragma unroll
    for (int p = 0; p < 4; p++) {
        __half h0 = __float2half_rn(w[p*2]),   h1 = __float2half_rn(w[p*2+1]);
        if (half) {
            __half l0 = __float2half_rn((w[p*2]   - __half2float(h0)) * 2048.f);
            __half l1 = __float2half_rn((w[p*2+1] - __half2float(h1)) * 2048.f);
            pk[p] = (uint32_t)__half_as_ushort(l0) | ((uint32_t)__half_as_ushort(l1) << 16);
        } else {
            pk[p] = (uint32_t)__half_as_ushort(h0) | ((uint32_t)__half_as_ushort(h1) << 16);
        }
    }
    g_pa[(size_t)vt*2048 + ks*64 + half*32 + lane] = make_uint4(pk[0], pk[1], pk[2], pk[3]);
}

// ---------------- the persistent kernel ----------------
union USm {
    struct { float wt[64][129]; float it[GG*64]; } p0;
    float smd[GG*268];
    float attrs_s[AA];
};

// GRU-gate GEMM item: 128 gate rows x 64 K (used for gh)
template<int KIN>
__device__ __forceinline__ void gemm_item(
    USm& u, const float* __restrict__ W, int j0, int kk0, int slot,
    const float* __restrict__ hraw, const float* __restrict__ emb, const int* s_tok,
    int tid, int warp, int lane)
{
    for (int idx = tid; idx < 128*16; idx += NTH) {
        int jl = idx >> 4, q = idx & 15;
        float4 w4 = *reinterpret_cast<const float4*>(&W[(size_t)(j0+jl)*KIN + kk0 + q*4]);
        u.p0.wt[q*4+0][jl] = w4.x; u.p0.wt[q*4+1][jl] = w4.y;
        u.p0.wt[q*4+2][jl] = w4.z; u.p0.wt[q*4+3][jl] = w4.w;
    }
    for (int idx = tid; idx < GG*16; idx += NTH) {
        int g = idx >> 4, q = idx & 15;
        const float* src = hraw ? &hraw[(size_t)g*HH] : &emb[(size_t)s_tok[g]*EE];
        *reinterpret_cast<float4*>(&u.p0.it[g*64 + q*4]) =
            *reinterpret_cast<const float4*>(&src[kk0 + q*4]);
    }
    __syncthreads();
    {
        int ty = warp & 7, ci0 = (warp >> 3) * 2;
        float acc[2][5] = {};
        for (int kk = 0; kk < 64; kk++) {
            float wv0 = u.p0.wt[kk][ci0*32 + lane];
            float wv1 = u.p0.wt[kk][(ci0+1)*32 + lane];
            #pragma unroll
            for (int rr = 0; rr < 5; rr++) {
                float xv = u.p0.it[(ty + 8*rr)*64 + kk];
                acc[0][rr] += wv0 * xv;
                acc[1][rr] += wv1 * xv;
            }
        }
        #pragma unroll
        for (int rr = 0; rr < 5; rr++) {
            int g = ty + 8*rr;
            g_gp[slot][g*1536 + j0 + ci0*32 + lane]     = acc[0][rr];
            g_gp[slot][g*1536 + j0 + (ci0+1)*32 + lane] = acc[1][rr];
        }
    }
}

// GRU-gate GEMM item: 64 gate rows x 64 K (used for gi; half-size item, same per-output
// kk-ascending FMA chain => bit-identical results, just finer work partitioning)
__device__ __forceinline__ void gemm_item64(
    USm& u, const float* __restrict__ W, int j0, int kk0, int slot,
    const float* __restrict__ emb, const int* s_tok,
    int tid, int warp, int lane)
{
    for (int idx = tid; idx < 64*16; idx += NTH) {
        int jl = idx >> 4, q = idx & 15;
        float4 w4 = *reinterpret_cast<const float4*>(&W[(size_t)(j0+jl)*EE + kk0 + q*4]);
        u.p0.wt[q*4+0][jl] = w4.x; u.p0.wt[q*4+1][jl] = w4.y;
        u.p0.wt[q*4+2][jl] = w4.z; u.p0.wt[q*4+3][jl] = w4.w;
    }
    for (int idx = tid; idx < GG*16; idx += NTH) {
        int g = idx >> 4, q = idx & 15;
        const float* src = &emb[(size_t)s_tok[g]*EE];
        *reinterpret_cast<float4*>(&u.p0.it[g*64 + q*4]) =
            *reinterpret_cast<const float4*>(&src[kk0 + q*4]);
    }
    __syncthreads();
    {
        int ty = warp & 7, ci = warp >> 3;      // 2 chunks of 32 cols
        float acc[5] = {};
        for (int kk = 0; kk < 64; kk++) {
            float wv = u.p0.wt[kk][ci*32 + lane];
            #pragma unroll
            for (int rr = 0; rr < 5; rr++) {
                float xv = u.p0.it[(ty + 8*rr)*64 + kk];
                acc[rr] += wv * xv;
            }
        }
        #pragma unroll
        for (int rr = 0; rr < 5; rr++) {
            int g = ty + 8*rr;
            g_gp[slot][g*1536 + j0 + ci*32 + lane] = acc[rr];
        }
    }
}

__global__ void __launch_bounds__(NTH)
k_main(const float* __restrict__ attrs, const int* __restrict__ bos,
       const float* __restrict__ emb,
       const float* __restrict__ w_ih, const float* __restrict__ b_ih,
       const float* __restrict__ w_hh, const float* __restrict__ b_hh,
       const float* __restrict__ tw,   const float* __restrict__ tb,
       const float* __restrict__ lb) {
    __shared__ USm u;
    __shared__ float s_bp[GG];
    __shared__ int   s_org[GG], s_tok[GG];

    const int bx = blockIdx.x, tid = threadIdx.x;
    const int warp = tid >> 5, lane = tid & 31;
    int gen = 0;

    if (bx < BB) {
        int b = bx;
        for (int i = tid; i < AA; i += NTH) u.attrs_s[i] = attrs[b*AA + i];
        __syncthreads();
        for (int j = tid; j < HH; j += NTH) {
            const float* wr = &tw[(size_t)j*AA];
            float acc = 0.f;
            for (int a = 0; a < AA; a++) acc += u.attrs_s[a] * wr[a];
            acc += tb[j];
            for (int k = 0; k < KK; k++) g_hn[0][(k*BB + b)*HH + j] = acc;
        }
    }
    if (tid < GG) {
        s_bp[tid]  = (tid < BB) ? 0.f : NEGF;
        s_org[tid] = tid / BB;
        s_tok[tid] = bos[0];
    }
    gbar(++gen);

    // prologue: speculative gh partials for step 0 from raw g_hn[0]
    if (bx >= 5 && bx < 101) {
        int it2 = bx - 5;
        int c = it2 / 12, jt = it2 % 12;
        gemm_item<HH>(u, w_hh, jt*128, c*64, 4 + c, g_hn[0], emb, s_tok, tid, warp, lane);
    }
    gbar(++gen);

    for (int t = 0; t < TT; t++) {
        const int prev = t & 1, cur = prev ^ 1;

        // ===== P0: gi gate GEMM (96 items of 64 rows, token-dependent) =====
        if (bx < 96) {
            int c = bx / 24, jt = bx % 24;
            gemm_item64(u, w_ih, jt*64, c*64, c, emb, s_tok, tid, warp, lane);
        }
        gbar(++gen);

        // ===== P1: gates + hn + B fragment pack (gh gathered via s_org) =====
        {
            int gid = bx*164 + tid;
            if (tid < 164 && gid < GG*HH) {
                int g = gid >> 9, j = gid & 511, b = g % BB;
                int graw = s_org[g]*BB + b;
                float gi0 = b_ih[j], gi1 = b_ih[HH+j], gi2 = b_ih[2*HH+j];
                float gh0 = b_hh[j], gh1 = b_hh[HH+j], gh2 = b_hh[2*HH+j];
                #pragma unroll
                for (int c = 0; c < 4; c++) {
                    const float* p = &g_gp[c][g*1536];
                    gi0 += p[j]; gi1 += p[HH+j]; gi2 += p[2*HH+j];
                }
                #pragma unroll
                for (int c = 4; c < 12; c++) {
                    const float* p = &g_gp[c][graw*1536];
                    gh0 += p[j]; gh1 += p[HH+j]; gh2 += p[2*HH+j];
                }
                float hprev = g_hn[prev][graw*HH + j];
                float rg = 1.f / (1.f + expf(-(gi0 + gh0)));
                float zg = 1.f / (1.f + expf(-(gi1 + gh1)));
                float ng = tanhf(gi2 + rg*gh2);
                float hv = (1.f - zg)*ng + zg*hprev;
                g_hn[cur][g*HH + j] = hv;

                int nt = g >> 3, gr = g & 7;
                int ks = j >> 4, rr = j & 15;
                int reg = rr >> 3, i4 = (rr & 7) >> 1, hb = rr & 1;
                int ln = gr*4 + i4;
                int e = (nt*32 + ks)*32 + ln;
                __half bh = __float2half_rn(hv);
                __half bl = __float2half_rn((hv - __half2float(bh)) * 2048.f);
                g_pb[e*8 + reg*2 + hb]     = bh;
                g_pb[e*8 + 4 + reg*2 + hb] = bl;
            }
        }
        gbar(++gen);

        // ===== P2: vocab MMA (16 warps x 1 mtile, proven form) + fused stats =====
        {
            const int item = bx, v0 = item * 256;
            const int vt = item*16 + warp;
            const uint4* pA = &g_pa[(size_t)vt*2048 + lane];
            const uint4* pB = reinterpret_cast<const uint4*>(g_pb) + lane;
            float a1[NT][4] = {}, a2[NT][4] = {};
            #pragma unroll 2
            for (int ks = 0; ks < 32; ks++) {
                uint4 Ah = pA[ks*64];
                uint4 Al = pA[ks*64 + 32];
                #pragma unroll
                for (int nt = 0; nt < NT; nt++) {
                    uint4 B = pB[(nt*32 + ks)*32];
                    MMA16(a1[nt], Ah, B.x, B.y);
                    MMA16(a2[nt], Ah, B.z, B.w);
                    MMA16(a2[nt], Al, B.x, B.y);
                }
            }
            #pragma unroll
            for (int nt = 0; nt < NT; nt++) {
                #pragma unroll
                for (int c = 0; c < 4; c++) {
                    float val = a1[nt][c] + a2[nt][c] * (1.f/2048.f);
                    int g = nt*8 + (lane & 3)*2 + (c & 1);
                    int vloc = warp*16 + (lane >> 2) + 8*(c >> 1);
                    u.smd[g*268 + vloc] = val;
                }
            }
            __syncthreads();
            for (int g = warp; g < GG; g += 16) {
                const float4* rp = reinterpret_cast<const float4*>(&u.smd[g*268]);
                float4 x0 = rp[lane], x1 = rp[lane + 32];
                float4 b0 = *reinterpret_cast<const float4*>(&lb[v0 + lane*4]);
                float4 b1 = *reinterpret_cast<const float4*>(&lb[v0 + 128 + lane*4]);
                x0.x += b0.x; x0.y += b0.y; x0.z += b0.z; x0.w += b0.w;
                x1.x += b1.x; x1.y += b1.y; x1.z += b1.z; x1.w += b1.w;
                float* dst = &g_out_all[((size_t)t*GG + g)*VV + v0];
                *reinterpret_cast<float4*>(dst + lane*4)       = x0;
                *reinterpret_cast<float4*>(dst + 128 + lane*4) = x1;

                float vv[8] = {x0.x, x0.y, x0.z, x0.w, x1.x, x1.y, x1.z, x1.w};
                float m = vv[0];
                #pragma unroll
                for (int i = 1; i < 8; i++) m = fmaxf(m, vv[i]);
                for (int o = 16; o; o >>= 1) m = fmaxf(m, __shfl_xor_sync(~0u, m, o));
                float s = 0.f;
                #pragma unroll
                for (int i = 0; i < 8; i++) s += expf(vv[i] - m);
                for (int o = 16; o; o >>= 1) s += __shfl_xor_sync(~0u, s, o);
                float t5[5]; int i5[5];
                #pragma unroll
                for (int i = 0; i < 5; i++) { t5[i] = -1e38f; i5[i] = 0x7fffffff; }
                #pragma unroll
                for (int i = 0; i < 4; i++) ins5(t5, i5, vv[i], v0 + lane*4 + i);
                #pragma unroll
                for (int i = 0; i < 4; i++) ins5(t5, i5, vv[4+i], v0 + 128 + lane*4 + i);
                float rv[5]; int ri[5];
                warp_top5(t5, i5, rv, ri);
                if (lane == 0) {
                    g_pm[item*GG + g] = m;
                    g_ps[item*GG + g] = s;
                    #pragma unroll
                    for (int q = 0; q < 5; q++) {
                        g_pv[(item*GG + g)*5 + q] = rv[q];
                        g_pi[(item*GG + g)*5 + q] = ri[q];
                    }
                }
            }
            __syncthreads();
        }
        gbar(++gen);

        // ===== P3: reduce (blocks 0-4) + speculative gh for t+1 (blocks 5-100) =====
        if (bx < 5) {
            if (warp < 8) {
                int g = bx*8 + warp;
                float m = -1e38f;
                for (int p = lane; p < NB; p += 32) m = fmaxf(m, g_pm[p*GG + g]);
                for (int o = 16; o; o >>= 1) m = fmaxf(m, __shfl_xor_sync(~0u, m, o));
                float s = 0.f;
                float t5[5]; int i5[5];
                #pragma unroll
                for (int i = 0; i < 5; i++) { t5[i] = -1e38f; i5[i] = 0x7fffffff; }
                for (int p = lane; p < NB; p += 32) {
                    s += g_ps[p*GG + g] * expf(g_pm[p*GG + g] - m);
                    #pragma unroll
                    for (int q = 0; q < 5; q++)
                        ins5(t5, i5, g_pv[(p*GG + g)*5 + q], g_pi[(p*GG + g)*5 + q]);
                }
                for (int o = 16; o; o >>= 1) s += __shfl_xor_sync(~0u, s, o);
                float rv[5]; int ri[5];
                warp_top5(t5, i5, rv, ri);
                if (lane == 0) {
                    #pragma unroll
                    for (int q = 0; q < 5; q++) { g_tv[g][q] = rv[q]; g_ti[g][q] = ri[q]; }
                    g_mx[g] = m;
                    g_ls[g] = logf(s);
                }
            }
        } else if (bx < 101 && t < TT-1) {
            int it2 = bx - 5;
            int c = it2 / 12, jt = it2 % 12;
            gemm_item<HH>(u, w_hh, jt*128, c*64, 4 + c, g_hn[cur], emb, s_tok, tid, warp, lane);
        }
        gbar(++gen);

        // ===== combine (redundant per block) =====
        if (tid < BB) {
            int b = tid;
            float cv[KK*KK]; int ct[KK*KK];
            #pragma unroll
            for (int ko = 0; ko < KK; ko++) {
                int gg = ko*BB + b;
                float Mg = g_mx[gg], Lg = g_ls[gg], bpv = s_bp[gg];
                #pragma unroll
                for (int q = 0; q < KK; q++) {
                    cv[ko*KK + q] = bpv + ((g_tv[gg][q] - Mg) - Lg);
                    ct[ko*KK + q] = g_ti[gg][q];
                }
            }
            float nbp[KK]; int norg[KK], ntok[KK];
            bool used[KK*KK] = {};
            #pragma unroll
            for (int kn = 0; kn < KK; kn++) {
                int bf = -1; float bv = 0.f;
                for (int f = 0; f < KK*KK; f++)
                    if (!used[f] && (bf < 0 || cv[f] > bv)) { bv = cv[f]; bf = f; }
                used[bf] = true;
                nbp[kn] = bv; norg[kn] = bf / KK; ntok[kn] = ct[bf];
            }
            #pragma unroll
            for (int kn = 0; kn < KK; kn++) {
                s_bp[kn*BB + b]  = nbp[kn];
                s_org[kn*BB + b] = norg[kn];
                s_tok[kn*BB + b] = ntok[kn];
                if (bx == 0) {
                    g_org_all[t*BB*KK + b*KK + kn] = norg[kn];
                    g_tok_all[t*BB*KK + b*KK + kn] = ntok[kn];
                }
            }
        }
        __syncthreads();
    }

    // ===== backtrack (block 0 only) =====
    if (bx == 0 && tid < BB*KK) {
        int b = tid / KK, k = tid % KK, idx = k;
        for (int t = TT - 1; t >= 0; t--) {
            int o = g_org_all[t*BB*KK + b*KK + idx];
            g_bt_slot[(b*KK + k)*TT + t] = o;
            g_bt_tok [(b*KK + k)*TT + t] = g_tok_all[t*BB*KK + b*KK + idx];
            idx = o;
        }
    }
}

// ---------------- final write ----------------
__global__ void k_write(float* __restrict__ out) {
    int q = blockIdx.x;
    int b = q / (KK*TT), rem = q % (KK*TT);
    int k = rem / TT, t = rem % TT;
    int s = g_bt_slot[(b*KK + k)*TT + t];
    int tok = g_bt_tok[(b*KK + k)*TT + t];
    const float4* src = (const float4*)&g_out_all[((size_t)t*GG + (s*BB + b))*VV];
    size_t N = (size_t)BB*KK*TT*VV;
    size_t off = (((size_t)b*KK + k)*TT + t)*(size_t)VV;
    float4* d0 = (float4*)(out + off);
    float4* d1 = (float4*)(out + N + off);
    float4* d2 = (float4*)(out + 2*N + off);
    for (int i = threadIdx.x; i < VV/4; i += blockDim.x) {
        d0[i] = src[i];
        int vb = i*4;
        float4 h;
        h.x = (vb == tok) ? 1.f : 0.f;  h.y = (vb+1 == tok) ? 1.f : 0.f;
        h.z = (vb+2 == tok) ? 1.f : 0.f; h.w = (vb+3 == tok) ? 1.f : 0.f;
        d1[i] = h; d2[i] = h;
    }
}

// ---------------- launch ----------------
extern "C" void kernel_launch(void* const* d_in, const int* in_sizes, int n_in,
                              void* d_out, int out_size) {
    const float* attrs = (const float*)d_in[0];
    const int*   bos   = (const int*)  d_in[1];
    const float* emb   = (const float*)d_in[4];
    const float* w_ih  = (const float*)d_in[5];
    const float* b_ih  = (const float*)d_in[6];
    const float* w_hh  = (const float*)d_in[7];
    const float* b_hh  = (const float*)d_in[8];
    const float* tw    = (const float*)d_in[9];
    const float* tb    = (const float*)d_in[10];
    const float* lw    = (const float*)d_in[11];
    const float* lb    = (const float*)d_in[12];
    float* out = (float*)d_out;

    k_reset<<<1, 128>>>();
    k_prep<<<(NVT*2048 + 255)/256, 256>>>(lw);
    k_main<<<NB, NTH>>>(attrs, bos, emb, w_ih, b_ih, w_hh, b_hh, tw, tb, lb);
    k_write<<<BB*KK*TT, 256>>>(out);
}

// round 17
// speedup vs baseline: 1.1419x; 1.0384x over previous
#include <cuda_runtime.h>
#include <cuda_fp16.h>
#include <cstdint>

#define BB 8
#define KK 5
#define TT 40
#define VV 32000
#define EE 256
#define HH 512
#define AA 512
#define GG 40
#define NEGF (-1e9f)
#define NB 125
#define NTH 512
#define NT 5
#define NVT 2000
#define BSZ (NT*32*32*8)            /* __half count = 40960, 80 KB */
#define BSZ16 (BSZ/8)               /* uint4 count = 5120 */

__device__ __forceinline__ bool better(float av, int ai, float bv, int bi) {
    return (av > bv) || (av == bv && ai < bi);
}
__device__ __forceinline__ void ins5(float* tv, int* ti, float v, int i) {
    if (better(v, i, tv[4], ti[4])) {
        tv[4] = v; ti[4] = i;
        #pragma unroll
        for (int j = 4; j > 0; j--)
            if (better(tv[j], ti[j], tv[j-1], ti[j-1])) {
                float fv = tv[j]; tv[j] = tv[j-1]; tv[j-1] = fv;
                int fi = ti[j]; ti[j] = ti[j-1]; ti[j-1] = fi;
            }
    }
}
__device__ __forceinline__ void warp_top5(float* tv, int* ti, float* rv, int* ri) {
    int hp = 0;
    #pragma unroll
    for (int s5 = 0; s5 < 5; s5++) {
        float bv = (hp < 5) ? tv[hp] : -1e38f;
        int   bi = (hp < 5) ? ti[hp] : 0x7fffffff;
        float wv = bv; int wi = bi;
        for (int o = 16; o; o >>= 1) {
            float ov = __shfl_xor_sync(~0u, wv, o);
            int   oi = __shfl_xor_sync(~0u, wi, o);
            if (better(ov, oi, wv, wi)) { wv = ov; wi = oi; }
        }
        rv[s5] = wv; ri[s5] = wi;
        if (hp < 5 && wi == bi && wv == bv) hp++;
    }
}
#define MMA16(c, A, b0, b1) \
    asm volatile("mma.sync.aligned.m16n8k16.row.col.f32.f16.f16.f32 " \
        "{%0,%1,%2,%3},{%4,%5,%6,%7},{%8,%9},{%0,%1,%2,%3};" \
        : "+f"((c)[0]), "+f"((c)[1]), "+f"((c)[2]), "+f"((c)[3]) \
        : "r"((A).x), "r"((A).y), "r"((A).z), "r"((A).w), "r"(b0), "r"(b1))

// ---------------- device state ----------------
__device__ float g_hn[2][GG*HH];
__device__ float g_gp[12][GG*1536];                 // 0-3: gi (token rows); 4-11: gh (RAW rows)
__device__ __align__(16) uint4 g_pa[(size_t)NVT*2048];  // per vtile: [ks][0..31]=Ah, [ks][32..63]=Al
__device__ __align__(16) __half g_pb[BSZ];          // [e]{bh0..3, bl0..3}
__device__ __align__(16) float g_out_all[(size_t)TT*GG*VV];
__device__ float g_pm[NB*GG];
__device__ float g_ps[NB*GG];
__device__ float g_pv[NB*GG*5];
__device__ int   g_pi[NB*GG*5];
__device__ float g_tv[GG][5];
__device__ int   g_ti[GG][5];
__device__ float g_mx[GG];
__device__ float g_ls[GG];
__device__ int   g_org_all[TT*BB*KK];
__device__ int   g_tok_all[TT*BB*KK];
__device__ int   g_bt_slot[BB*KK*TT];
__device__ int   g_bt_tok [BB*KK*TT];
__device__ int   g_flags[NB];
__device__ int   g_rel;

// flag-array barrier (execution-proven): parallel arrivals, block 0 aggregates.
__device__ __forceinline__ void gbar(int gen) {
    __syncthreads();
    if (threadIdx.x == 0) {
        __threadfence();
        *(volatile int*)&g_flags[blockIdx.x] = gen;
    }
    if (blockIdx.x == 0) {
        if (threadIdx.x < NB)
            while (*(volatile int*)&g_flags[threadIdx.x] < gen) { }
        __syncthreads();
        if (threadIdx.x == 0) { __threadfence(); *(volatile int*)&g_rel = gen; }
    }
    if (threadIdx.x == 0) {
        while (*(volatile int*)&g_rel < gen) { }
        __threadfence();
    }
    __syncthreads();
}

__global__ void k_reset() {
    if (threadIdx.x < NB) g_flags[threadIdx.x] = 0;
    if (threadIdx.x == 0) g_rel = 0;
}

// ---------------- weight fp16-split fragment prep (once; scaled residual) ----------------
__global__ void k_prep(const float* __restrict__ lw) {
    int idx = blockIdx.x*256 + threadIdx.x;
    if (idx >= NVT*2048) return;
    int lane = idx & 31, half = (idx >> 5) & 1, ks = (idx >> 6) & 31, vt = idx >> 11;
    int m0 = vt*16 + (lane >> 2), m1 = m0 + 8;
    int k0 = ks*16 + (lane & 3)*2;
    const float* r0 = &lw[(size_t)m0*HH];
    const float* r1 = &lw[(size_t)m1*HH];
    float w[8] = { r0[k0], r0[k0+1], r1[k0], r1[k0+1],
                   r0[k0+8], r0[k0+9], r1[k0+8], r1[k0+9] };
    uint32_t pk[4];
    #pragma unroll
    for (int p = 0; p < 4; p++) {
        __half h0 = __float2half_rn(w[p*2]),   h1 = __float2half_rn(w[p*2+1]);
        if (half) {
            __half l0 = __float2half_rn((w[p*2]   - __half2float(h0)) * 2048.f);
            __half l1 = __float2half_rn((w[p*2+1] - __half2float(h1)) * 2048.f);
            pk[p] = (uint32_t)__half_as_ushort(l0) | ((uint32_t)__half_as_ushort(l1) << 16);
        } else {
            pk[p] = (uint32_t)__half_as_ushort(h0) | ((uint32_t)__half_as_ushort(h1) << 16);
        }
    }
    g_pa[(size_t)vt*2048 + ks*64 + half*32 + lane] = make_uint4(pk[0], pk[1], pk[2], pk[3]);
}

// ---------------- the persistent kernel ----------------
union USm {
    struct { float wt[64][129]; float it[GG*64]; } p0;
    float smd[GG*268];
    float attrs_s[AA];
};

// one GRU-gate GEMM item: 128 gate rows x 64 K
template<int KIN>
__device__ __forceinline__ void gemm_item(
    USm& u, const float* __restrict__ W, int j0, int kk0, int slot,
    const float* __restrict__ hraw, const float* __restrict__ emb, const int* s_tok,
    int tid, int warp, int lane)
{
    for (int idx = tid; idx < 128*16; idx += NTH) {
        int jl = idx >> 4, q = idx & 15;
        float4 w4 = *reinterpret_cast<const float4*>(&W[(size_t)(j0+jl)*KIN + kk0 + q*4]);
        u.p0.wt[q*4+0][jl] = w4.x; u.p0.wt[q*4+1][jl] = w4.y;
        u.p0.wt[q*4+2][jl] = w4.z; u.p0.wt[q*4+3][jl] = w4.w;
    }
    for (int idx = tid; idx < GG*16; idx += NTH) {
        int g = idx >> 4, q = idx & 15;
        const float* src = hraw ? &hraw[(size_t)g*HH] : &emb[(size_t)s_tok[g]*EE];
        *reinterpret_cast<float4*>(&u.p0.it[g*64 + q*4]) =
            *reinterpret_cast<const float4*>(&src[kk0 + q*4]);
    }
    __syncthreads();
    {
        int ty = warp & 7, ci0 = (warp >> 3) * 2;
        float acc[2][5] = {};
        for (int kk = 0; kk < 64; kk++) {
            float wv0 = u.p0.wt[kk][ci0*32 + lane];
            float wv1 = u.p0.wt[kk][(ci0+1)*32 + lane];
            #pragma unroll
            for (int rr = 0; rr < 5; rr++) {
                float xv = u.p0.it[(ty + 8*rr)*64 + kk];
                acc[0][rr] += wv0 * xv;
                acc[1][rr] += wv1 * xv;
            }
        }
        #pragma unroll
        for (int rr = 0; rr < 5; rr++) {
            int g = ty + 8*rr;
            g_gp[slot][g*1536 + j0 + ci0*32 + lane]     = acc[0][rr];
            g_gp[slot][g*1536 + j0 + (ci0+1)*32 + lane] = acc[1][rr];
        }
    }
}

__global__ void __launch_bounds__(NTH)
k_main(const float* __restrict__ attrs, const int* __restrict__ bos,
       const float* __restrict__ emb,
       const float* __restrict__ w_ih, const float* __restrict__ b_ih,
       const float* __restrict__ w_hh, const float* __restrict__ b_hh,
       const float* __restrict__ tw,   const float* __restrict__ tb,
       const float* __restrict__ lb) {
    extern __shared__ __align__(16) uint4 sB[];     // 80 KB dynamic: staged B fragments
    __shared__ USm u;
    __shared__ float s_bp[GG];
    __shared__ int   s_org[GG], s_tok[GG];

    const int bx = blockIdx.x, tid = threadIdx.x;
    const int warp = tid >> 5, lane = tid & 31;
    int gen = 0;

    if (bx < BB) {
        int b = bx;
        for (int i = tid; i < AA; i += NTH) u.attrs_s[i] = attrs[b*AA + i];
        __syncthreads();
        for (int j = tid; j < HH; j += NTH) {
            const float* wr = &tw[(size_t)j*AA];
            float acc = 0.f;
            for (int a = 0; a < AA; a++) acc += u.attrs_s[a] * wr[a];
            acc += tb[j];
            for (int k = 0; k < KK; k++) g_hn[0][(k*BB + b)*HH + j] = acc;
        }
    }
    if (tid < GG) {
        s_bp[tid]  = (tid < BB) ? 0.f : NEGF;
        s_org[tid] = tid / BB;
        s_tok[tid] = bos[0];
    }
    gbar(++gen);

    // prologue: speculative gh partials for step 0 from raw g_hn[0]
    if (bx >= 5 && bx < 101) {
        int it2 = bx - 5;
        int c = it2 / 12, jt = it2 % 12;
        gemm_item<HH>(u, w_hh, jt*128, c*64, 4 + c, g_hn[0], emb, s_tok, tid, warp, lane);
    }
    gbar(++gen);

    for (int t = 0; t < TT; t++) {
        const int prev = t & 1, cur = prev ^ 1;

        // ===== P0: gi gate GEMM only (48 items of 128 rows) =====
        if (bx < 48) {
            int c = bx / 12, jt = bx % 12;
            gemm_item<EE>(u, w_ih, jt*128, c*64, c, nullptr, emb, s_tok, tid, warp, lane);
        }
        gbar(++gen);

        // ===== P1: gates + hn + B fragment pack (gh gathered via s_org) =====
        {
            int gid = bx*164 + tid;
            if (tid < 164 && gid < GG*HH) {
                int g = gid >> 9, j = gid & 511, b = g % BB;
                int graw = s_org[g]*BB + b;
                float gi0 = b_ih[j], gi1 = b_ih[HH+j], gi2 = b_ih[2*HH+j];
                float gh0 = b_hh[j], gh1 = b_hh[HH+j], gh2 = b_hh[2*HH+j];
                #pragma unroll
                for (int c = 0; c < 4; c++) {
                    const float* p = &g_gp[c][g*1536];
                    gi0 += p[j]; gi1 += p[HH+j]; gi2 += p[2*HH+j];
                }
                #pragma unroll
                for (int c = 4; c < 12; c++) {
                    const float* p = &g_gp[c][graw*1536];
                    gh0 += p[j]; gh1 += p[HH+j]; gh2 += p[2*HH+j];
                }
                float hprev = g_hn[prev][graw*HH + j];
                float rg = 1.f / (1.f + expf(-(gi0 + gh0)));
                float zg = 1.f / (1.f + expf(-(gi1 + gh1)));
                float ng = tanhf(gi2 + rg*gh2);
                float hv = (1.f - zg)*ng + zg*hprev;
                g_hn[cur][g*HH + j] = hv;

                int nt = g >> 3, gr = g & 7;
                int ks = j >> 4, rr = j & 15;
                int reg = rr >> 3, i4 = (rr & 7) >> 1, hb = rr & 1;
                int ln = gr*4 + i4;
                int e = (nt*32 + ks)*32 + ln;
                __half bh = __float2half_rn(hv);
                __half bl = __float2half_rn((hv - __half2float(bh)) * 2048.f);
                g_pb[e*8 + reg*2 + hb]     = bh;
                g_pb[e*8 + 4 + reg*2 + hb] = bl;
            }
        }
        gbar(++gen);

        // ===== P2: stage B in smem once, then vocab MMA (16 warps) + stats =====
        {
            const int item = bx, v0 = item * 256;
            // stage the 80 KB B fragment array: read ONCE per block from L2
            for (int i = tid; i < BSZ16; i += NTH)
                sB[i] = reinterpret_cast<const uint4*>(g_pb)[i];
            __syncthreads();

            const int vt = item*16 + warp;
            const uint4* pA = &g_pa[(size_t)vt*2048 + lane];
            const uint4* pB = sB + lane;
            float a1[NT][4] = {}, a2[NT][4] = {};
            #pragma unroll 2
            for (int ks = 0; ks < 32; ks++) {
                uint4 Ah = pA[ks*64];
                uint4 Al = pA[ks*64 + 32];
                #pragma unroll
                for (int nt = 0; nt < NT; nt++) {
                    uint4 B = pB[(nt*32 + ks)*32];
                    MMA16(a1[nt], Ah, B.x, B.y);
                    MMA16(a2[nt], Ah, B.z, B.w);
                    MMA16(a2[nt], Al, B.x, B.y);
                }
            }
            #pragma unroll
            for (int nt = 0; nt < NT; nt++) {
                #pragma unroll
                for (int c = 0; c < 4; c++) {
                    float val = a1[nt][c] + a2[nt][c] * (1.f/2048.f);
                    int g = nt*8 + (lane & 3)*2 + (c & 1);
                    int vloc = warp*16 + (lane >> 2) + 8*(c >> 1);
                    u.smd[g*268 + vloc] = val;
                }
            }
            __syncthreads();
            for (int g = warp; g < GG; g += 16) {
                const float4* rp = reinterpret_cast<const float4*>(&u.smd[g*268]);
                float4 x0 = rp[lane], x1 = rp[lane + 32];
                float4 b0 = *reinterpret_cast<const float4*>(&lb[v0 + lane*4]);
                float4 b1 = *reinterpret_cast<const float4*>(&lb[v0 + 128 + lane*4]);
                x0.x += b0.x; x0.y += b0.y; x0.z += b0.z; x0.w += b0.w;
                x1.x += b1.x; x1.y += b1.y; x1.z += b1.z; x1.w += b1.w;
                float* dst = &g_out_all[((size_t)t*GG + g)*VV + v0];
                *reinterpret_cast<float4*>(dst + lane*4)       = x0;
                *reinterpret_cast<float4*>(dst + 128 + lane*4) = x1;

                float vv[8] = {x0.x, x0.y, x0.z, x0.w, x1.x, x1.y, x1.z, x1.w};
                float m = vv[0];
                #pragma unroll
                for (int i = 1; i < 8; i++) m = fmaxf(m, vv[i]);
                for (int o = 16; o; o >>= 1) m = fmaxf(m, __shfl_xor_sync(~0u, m, o));
                float s = 0.f;
                #pragma unroll
                for (int i = 0; i < 8; i++) s += expf(vv[i] - m);
                for (int o = 16; o; o >>= 1) s += __shfl_xor_sync(~0u, s, o);
                float t5[5]; int i5[5];
                #pragma unroll
                for (int i = 0; i < 5; i++) { t5[i] = -1e38f; i5[i] = 0x7fffffff; }
                #pragma unroll
                for (int i = 0; i < 4; i++) ins5(t5, i5, vv[i], v0 + lane*4 + i);
                #pragma unroll
                for (int i = 0; i < 4; i++) ins5(t5, i5, vv[4+i], v0 + 128 + lane*4 + i);
                float rv[5]; int ri[5];
                warp_top5(t5, i5, rv, ri);
                if (lane == 0) {
                    g_pm[item*GG + g] = m;
                    g_ps[item*GG + g] = s;
                    #pragma unroll
                    for (int q = 0; q < 5; q++) {
                        g_pv[(item*GG + g)*5 + q] = rv[q];
                        g_pi[(item*GG + g)*5 + q] = ri[q];
                    }
                }
            }
            __syncthreads();
        }
        gbar(++gen);

        // ===== P3: reduce (blocks 0-4) + speculative gh for t+1 (blocks 5-100) =====
        if (bx < 5) {
            if (warp < 8) {
                int g = bx*8 + warp;
                float m = -1e38f;
                for (int p = lane; p < NB; p += 32) m = fmaxf(m, g_pm[p*GG + g]);
                for (int o = 16; o; o >>= 1) m = fmaxf(m, __shfl_xor_sync(~0u, m, o));
                float s = 0.f;
                float t5[5]; int i5[5];
                #pragma unroll
                for (int i = 0; i < 5; i++) { t5[i] = -1e38f; i5[i] = 0x7fffffff; }
                for (int p = lane; p < NB; p += 32) {
                    s += g_ps[p*GG + g] * expf(g_pm[p*GG + g] - m);
                    #pragma unroll
                    for (int q = 0; q < 5; q++)
                        ins5(t5, i5, g_pv[(p*GG + g)*5 + q], g_pi[(p*GG + g)*5 + q]);
                }
                for (int o = 16; o; o >>= 1) s += __shfl_xor_sync(~0u, s, o);
                float rv[5]; int ri[5];
                warp_top5(t5, i5, rv, ri);
                if (lane == 0) {
                    #pragma unroll
                    for (int q = 0; q < 5; q++) { g_tv[g][q] = rv[q]; g_ti[g][q] = ri[q]; }
                    g_mx[g] = m;
                    g_ls[g] = logf(s);
                }
            }
        } else if (bx < 101 && t < TT-1) {
            int it2 = bx - 5;
            int c = it2 / 12, jt = it2 % 12;
            gemm_item<HH>(u, w_hh, jt*128, c*64, 4 + c, g_hn[cur], emb, s_tok, tid, warp, lane);
        }
        gbar(++gen);

        // ===== combine (redundant per block) =====
        if (tid < BB) {
            int b = tid;
            float cv[KK*KK]; int ct[KK*KK];
            #pragma unroll
            for (int ko = 0; ko < KK; ko++) {
                int gg = ko*BB + b;
                float Mg = g_mx[gg], Lg = g_ls[gg], bpv = s_bp[gg];
                #pragma unroll
                for (int q = 0; q < KK; q++) {
                    cv[ko*KK + q] = bpv + ((g_tv[gg][q] - Mg) - Lg);
                    ct[ko*KK + q] = g_ti[gg][q];
                }
            }
            float nbp[KK]; int norg[KK], ntok[KK];
            bool used[KK*KK] = {};
            #pragma unroll
            for (int kn = 0; kn < KK; kn++) {
                int bf = -1; float bv = 0.f;
                for (int f = 0; f < KK*KK; f++)
                    if (!used[f] && (bf < 0 || cv[f] > bv)) { bv = cv[f]; bf = f; }
                used[bf] = true;
                nbp[kn] = bv; norg[kn] = bf / KK; ntok[kn] = ct[bf];
            }
            #pragma unroll
            for (int kn = 0; kn < KK; kn++) {
                s_bp[kn*BB + b]  = nbp[kn];
                s_org[kn*BB + b] = norg[kn];
                s_tok[kn*BB + b] = ntok[kn];
                if (bx == 0) {
                    g_org_all[t*BB*KK + b*KK + kn] = norg[kn];
                    g_tok_all[t*BB*KK + b*KK + kn] = ntok[kn];
                }
            }
        }
        __syncthreads();
    }

    // ===== backtrack (block 0 only) =====
    if (bx == 0 && tid < BB*KK) {
        int b = tid / KK, k = tid % KK, idx = k;
        for (int t = TT - 1; t >= 0; t--) {
            int o = g_org_all[t*BB*KK + b*KK + idx];
            g_bt_slot[(b*KK + k)*TT + t] = o;
            g_bt_tok [(b*KK + k)*TT + t] = g_tok_all[t*BB*KK + b*KK + idx];
            idx = o;
        }
    }
}

// ---------------- final write ----------------
__global__ void k_write(float* __restrict__ out) {
    int q = blockIdx.x;
    int b = q / (KK*TT), rem = q % (KK*TT);
    int k = rem / TT, t = rem % TT;
    int s = g_bt_slot[(b*KK + k)*TT + t];
    int tok = g_bt_tok[(b*KK + k)*TT + t];
    const float4* src = (const float4*)&g_out_all[((size_t)t*GG + (s*BB + b))*VV];
    size_t N = (size_t)BB*KK*TT*VV;
    size_t off = (((size_t)b*KK + k)*TT + t)*(size_t)VV;
    float4* d0 = (float4*)(out + off);
    float4* d1 = (float4*)(out + N + off);
    float4* d2 = (float4*)(out + 2*N + off);
    for (int i = threadIdx.x; i < VV/4; i += blockDim.x) {
        d0[i] = src[i];
        int vb = i*4;
        float4 h;
        h.x = (vb == tok) ? 1.f : 0.f;  h.y = (vb+1 == tok) ? 1.f : 0.f;
        h.z = (vb+2 == tok) ? 1.f : 0.f; h.w = (vb+3 == tok) ? 1.f : 0.f;
        d1[i] = h; d2[i] = h;
    }
}

// ---------------- launch ----------------
extern "C" void kernel_launch(void* const* d_in, const int* in_sizes, int n_in,
                              void* d_out, int out_size) {
    const float* attrs = (const float*)d_in[0];
    const int*   bos   = (const int*)  d_in[1];
    const float* emb   = (const float*)d_in[4];
    const float* w_ih  = (const float*)d_in[5];
    const float* b_ih  = (const float*)d_in[6];
    const float* w_hh  = (const float*)d_in[7];
    const float* b_hh  = (const float*)d_in[8];
    const float* tw    = (const float*)d_in[9];
    const float* tb    = (const float*)d_in[10];
    const float* lw    = (const float*)d_in[11];
    const float* lb    = (const float*)d_in[12];
    float* out = (float*)d_out;

    static int smem_set = 0;
    if (!smem_set) {
        cudaFuncSetAttribute(k_main, cudaFuncAttributeMaxDynamicSharedMemorySize, BSZ*2);
        smem_set = 1;
    }

    k_reset<<<1, 128>>>();
    k_prep<<<(NVT*2048 + 255)/256, 256>>>(lw);
    k_main<<<NB, NTH, BSZ*2>>>(attrs, bos, emb, w_ih, b_ih, w_hh, b_hh, tw, tb, lb);
    k_write<<<BB*KK*TT, 256>>>(out);
}